// round 4
// baseline (speedup 1.0000x reference)
#include <cuda_runtime.h>
#include <cuda_bf16.h>
#include <limits.h>

// Sorted-segment-sum of gathered values:
//   out[s] = sum over j with seg[j]==s of cv[idx[j]]
// seg[] sorted ascending. Empty segments must be 0 (out is poisoned).
//
// Single-wave persistent launch: exactly NBLOCKS = 148*8 CTAs; each warp owns
// one contiguous balanced range of 256-edge chunks. Per chunk: 8 edges/thread
// via 2x int4 loads, per-thread run detection, ballot-based clamped warp scan
// over trailing runs, lane-31 carry chains across chunks -> ~1 atomic/segment.

#define FULL 0xffffffffu
#define CHUNK 256            // edges per warp per iteration (8/thread)
#define NBLOCKS 1184         // 148 SMs x 8 CTAs (one full wave at 256 thr, 32 reg)
#define WARPS_PER_BLK 8

__global__ void zero_out_kernel(float4* __restrict__ out4, int n4,
                                float* __restrict__ out, int n) {
    int i = blockIdx.x * blockDim.x + threadIdx.x;
    if (i < n4) out4[i] = make_float4(0.f, 0.f, 0.f, 0.f);
    int r = n4 * 4 + i;
    if (i < (n - n4 * 4)) out[r] = 0.0f;
}

__global__ __launch_bounds__(256, 8)
void seg_sum_kernel(const float* __restrict__ cv,
                    const int*   __restrict__ idx,
                    const int*   __restrict__ seg,
                    float*       __restrict__ out,
                    int E)
{
    const int lane = threadIdx.x & 31;
    const unsigned w =
        blockIdx.x * WARPS_PER_BLK + (threadIdx.x >> 5);   // global warp id
    const unsigned n_warps = NBLOCKS * WARPS_PER_BLK;

    // balanced contiguous chunk range for this warp
    const unsigned long long chunks_total =
        ((unsigned long long)E + CHUNK - 1) / CHUNK;
    const unsigned long long c_lo = chunks_total * w / n_warps;
    const unsigned long long c_hi = chunks_total * (w + 1) / n_warps;
    if (c_lo >= c_hi) return;

    long long base = (long long)c_lo * CHUNK;
    long long end  = (long long)c_hi * CHUNK;
    if (end > (long long)E) end = (long long)E;

    float carry     = 0.0f;
    int   carry_seg = -1;   // -1 = no pending carry

    const int4* idx4 = (const int4*)idx;
    const int4* seg4 = (const int4*)seg;

    long long p = base;
    for (; p + CHUNK <= end; p += CHUNK) {
        // each lane owns 2 consecutive int4's => 8 consecutive edges
        long long q = (p >> 2) + lane * 2;
        int4 sa = seg4[q];
        int4 sb = seg4[q + 1];
        int4 ia = idx4[q];
        int4 ib = idx4[q + 1];

        float v_arr[8];
        v_arr[0] = __ldg(&cv[ia.x]);
        v_arr[1] = __ldg(&cv[ia.y]);
        v_arr[2] = __ldg(&cv[ia.z]);
        v_arr[3] = __ldg(&cv[ia.w]);
        v_arr[4] = __ldg(&cv[ib.x]);
        v_arr[5] = __ldg(&cv[ib.y]);
        v_arr[6] = __ldg(&cv[ib.z]);
        v_arr[7] = __ldg(&cv[ib.w]);

        int s_arr[8] = { sa.x, sa.y, sa.z, sa.w, sb.x, sb.y, sb.z, sb.w };

        // per-thread run detection over 8 consecutive edges
        float run = v_arr[0];
        int   rs  = s_arr[0];
        const int sfirst = s_arr[0];
        float lead = 0.0f;
        bool  leadDone = false;
        #pragma unroll
        for (int i = 1; i < 8; i++) {
            if (s_arr[i] == rs) {
                run += v_arr[i];
            } else {
                if (!leadDone) { lead = run; leadDone = true; }
                else           { atomicAdd(&out[rs], run); }  // interior: complete
                run = v_arr[i];
                rs  = s_arr[i];
            }
        }
        const float trail   = run;     // if allsame: total of all 8
        const int   slast   = rs;
        const bool  allsame = !leadDone;

        // connectivity with preceding lane / iteration carry
        int  prev_slast = __shfl_up_sync(FULL, slast, 1);
        bool connected  = (lane == 0) ? (carry_seg == sfirst)
                                      : (prev_slast == sfirst);

        // scan input: trailing-run value; fold carry at lane 0 when the
        // whole thread is one run continuing the carry segment
        float sv = trail;
        if (lane == 0 && connected && allsame) sv += carry;
        bool f = (lane == 0) || !allsame || !connected;  // chain break

        // ballot-based clamped inclusive scan over trailing-run chain
        unsigned head_mask = __ballot_sync(FULL, f);     // bit0 always set
        unsigned mask_le   = head_mask & (FULL >> (31 - lane));
        int seg_start = 31 - __clz(mask_le);
        #pragma unroll
        for (int d = 1; d < 32; d <<= 1) {
            float y = __shfl_up_sync(FULL, sv, d);
            if (lane - d >= seg_start) sv += y;
        }

        // chain-sum ending at lane-1 (completed prefix for segment sfirst)
        float inc_prev = __shfl_up_sync(FULL, sv, 1);
        if (lane == 0) inc_prev = carry;

        // flush this thread's leading run (complete since !allsame)
        if (!allsame) {
            float add = lead + (connected ? inc_prev : 0.0f);
            atomicAdd(&out[sfirst], add);
        }
        // lane 0 disconnected: inter-iteration carry segment is complete
        if (lane == 0 && !connected && carry_seg >= 0) {
            atomicAdd(&out[carry_seg], carry);
        }

        // trailing-run flush: complete if the next lane doesn't continue it
        int  next_sfirst    = __shfl_down_sync(FULL, sfirst, 1);
        bool next_connected = (next_sfirst == slast);
        if (lane < 31 && !next_connected) {
            atomicAdd(&out[slast], sv);
        }

        // lane 31's chain becomes the carry
        carry     = __shfl_sync(FULL, sv, 31);
        carry_seg = __shfl_sync(FULL, slast, 31);
    }

    // scalar tail (final partial chunk, 32 edges at a time)
    for (; p < end; p += 32) {
        long long j = p + lane;
        bool valid  = (j < end);

        int   s = INT_MAX;
        float v = 0.0f;
        if (valid) {
            s = seg[j];
            v = __ldg(&cv[idx[j]]);
        }

        int  s_prev = __shfl_up_sync(FULL, s, 1);
        bool head   = (lane == 0) || (s != s_prev);
        unsigned head_mask = __ballot_sync(FULL, head);

        unsigned mask_le = head_mask & (FULL >> (31 - lane));
        int seg_start = 31 - __clz(mask_le);

        float x = v;
        #pragma unroll
        for (int d = 1; d < 32; d <<= 1) {
            float y = __shfl_up_sync(FULL, x, d);
            if (lane - d >= seg_start) x += y;
        }

        int s0 = __shfl_sync(FULL, s, 0);
        if (carry_seg == s0) {
            if (seg_start == 0) x += carry;
        } else if (carry_seg >= 0) {
            if (lane == 0) atomicAdd(&out[carry_seg], carry);
        }

        bool tail = (lane == 31) || ((head_mask >> (lane + 1)) & 1u);
        if (tail && lane != 31 && valid) {
            atomicAdd(&out[s], x);
        }

        carry   = __shfl_sync(FULL, x, 31);
        int s31 = __shfl_sync(FULL, s, 31);
        carry_seg = (s31 == INT_MAX) ? -1 : s31;
    }

    if (carry_seg >= 0 && lane == 0) {
        atomicAdd(&out[carry_seg], carry);
    }
}

extern "C" void kernel_launch(void* const* d_in, const int* in_sizes, int n_in,
                              void* d_out, int out_size)
{
    const float* cv  = (const float*)d_in[0];
    const int*   idx = (const int*)d_in[1];
    const int*   seg = (const int*)d_in[2];
    float*       out = (float*)d_out;

    const int E = in_sizes[1];
    const int N = out_size;

    {
        int n4 = N / 4;
        int threads = 256;
        int blocks  = (n4 + threads - 1) / threads;
        if (blocks < 1) blocks = 1;
        zero_out_kernel<<<blocks, threads>>>((float4*)out, n4, out, N);
    }
    seg_sum_kernel<<<NBLOCKS, 256>>>(cv, idx, seg, out, E);
}

// round 5
// speedup vs baseline: 1.1121x; 1.1121x over previous
#include <cuda_runtime.h>
#include <cuda_bf16.h>
#include <limits.h>

// Sorted-segment-sum of gathered values:
//   out[s] = sum over j with seg[j]==s of cv[idx[j]]
// seg[] sorted ascending. Empty segments must be 0 (out is poisoned).
//
// Fine-grained launch: each warp handles ONE 256-edge chunk (8 edges/thread
// via 2x int4 loads). Per-thread run detection; interior runs flush directly;
// trailing runs combined by a ballot-based clamped warp scan. Segments that
// span chunk boundaries cost one extra atomic (rare: ~E/256 cases).

#define FULL 0xffffffffu
#define CHUNK 256          // edges per warp (8 per thread)
#define WARPS_PER_BLK 8

__global__ void zero_out_kernel(float4* __restrict__ out4, int n4,
                                float* __restrict__ out, int n) {
    int i = blockIdx.x * blockDim.x + threadIdx.x;
    if (i < n4) out4[i] = make_float4(0.f, 0.f, 0.f, 0.f);
    int r = n4 * 4 + i;
    if (i < (n - n4 * 4)) out[r] = 0.0f;
}

__global__ __launch_bounds__(256, 8)
void seg_sum_kernel(const float* __restrict__ cv,
                    const int*   __restrict__ idx,
                    const int*   __restrict__ seg,
                    float*       __restrict__ out,
                    int E)
{
    const int lane = threadIdx.x & 31;
    const long long w =
        (long long)blockIdx.x * WARPS_PER_BLK + (threadIdx.x >> 5);

    long long base = w * (long long)CHUNK;
    if (base >= (long long)E) return;

    if (base + CHUNK <= (long long)E) {
        // ---------------- fast path: one full 256-edge chunk ----------------
        const int4* idx4 = (const int4*)idx;
        const int4* seg4 = (const int4*)seg;

        long long q = (base >> 2) + lane * 2;   // 2 consecutive int4 = 8 edges
        int4 sa = seg4[q];
        int4 sb = seg4[q + 1];
        int4 ia = idx4[q];
        int4 ib = idx4[q + 1];

        float v_arr[8];
        v_arr[0] = __ldg(&cv[ia.x]);
        v_arr[1] = __ldg(&cv[ia.y]);
        v_arr[2] = __ldg(&cv[ia.z]);
        v_arr[3] = __ldg(&cv[ia.w]);
        v_arr[4] = __ldg(&cv[ib.x]);
        v_arr[5] = __ldg(&cv[ib.y]);
        v_arr[6] = __ldg(&cv[ib.z]);
        v_arr[7] = __ldg(&cv[ib.w]);

        int s_arr[8] = { sa.x, sa.y, sa.z, sa.w, sb.x, sb.y, sb.z, sb.w };

        // per-thread run detection over 8 consecutive edges
        float run = v_arr[0];
        int   rs  = s_arr[0];
        const int sfirst = s_arr[0];
        float lead = 0.0f;
        bool  leadDone = false;
        #pragma unroll
        for (int i = 1; i < 8; i++) {
            if (s_arr[i] == rs) {
                run += v_arr[i];
            } else {
                if (!leadDone) { lead = run; leadDone = true; }
                else           { atomicAdd(&out[rs], run); }  // interior: complete
                run = v_arr[i];
                rs  = s_arr[i];
            }
        }
        const float trail   = run;     // if allsame: total of all 8
        const int   slast   = rs;
        const bool  allsame = !leadDone;

        // connectivity with the preceding lane
        int  prev_slast = __shfl_up_sync(FULL, slast, 1);
        bool connected  = (lane != 0) && (prev_slast == sfirst);

        float sv = trail;
        bool  f  = (lane == 0) || !allsame || !connected;  // chain break

        // ballot-based clamped inclusive scan over trailing-run chain
        unsigned head_mask = __ballot_sync(FULL, f);       // bit0 always set
        unsigned mask_le   = head_mask & (FULL >> (31 - lane));
        int seg_start = 31 - __clz(mask_le);
        #pragma unroll
        for (int d = 1; d < 32; d <<= 1) {
            float y = __shfl_up_sync(FULL, sv, d);
            if (lane - d >= seg_start) sv += y;
        }

        // chain-sum ending at lane-1 (completed prefix for segment sfirst)
        float inc_prev = __shfl_up_sync(FULL, sv, 1);

        // flush this thread's leading run (complete since !allsame)
        if (!allsame) {
            float add = lead + (connected ? inc_prev : 0.0f);
            atomicAdd(&out[sfirst], add);
        }

        // trailing-run flush: complete if the next lane doesn't continue it
        int  next_sfirst    = __shfl_down_sync(FULL, sfirst, 1);
        bool next_connected = (lane < 31) && (next_sfirst == slast);
        if (!next_connected) {
            atomicAdd(&out[slast], sv);   // lane 31 always flushes its chain
        }
    } else {
        // ---------------- scalar tail path (last partial chunk) ----------------
        long long lim = (long long)E;
        float carry     = 0.0f;
        int   carry_seg = -1;

        for (long long p = base; p < lim; p += 32) {
            long long j = p + lane;
            bool valid  = (j < lim);

            int   s = INT_MAX;
            float v = 0.0f;
            if (valid) {
                s = seg[j];
                v = __ldg(&cv[idx[j]]);
            }

            int  s_prev = __shfl_up_sync(FULL, s, 1);
            bool head   = (lane == 0) || (s != s_prev);
            unsigned head_mask = __ballot_sync(FULL, head);

            unsigned mask_le = head_mask & (FULL >> (31 - lane));
            int seg_start = 31 - __clz(mask_le);

            float x = v;
            #pragma unroll
            for (int d = 1; d < 32; d <<= 1) {
                float y = __shfl_up_sync(FULL, x, d);
                if (lane - d >= seg_start) x += y;
            }

            int s0 = __shfl_sync(FULL, s, 0);
            if (carry_seg == s0) {
                if (seg_start == 0) x += carry;
            } else if (carry_seg >= 0) {
                if (lane == 0) atomicAdd(&out[carry_seg], carry);
            }

            bool tail = (lane == 31) || ((head_mask >> (lane + 1)) & 1u);
            if (tail && lane != 31 && valid) {
                atomicAdd(&out[s], x);
            }

            carry   = __shfl_sync(FULL, x, 31);
            int s31 = __shfl_sync(FULL, s, 31);
            carry_seg = (s31 == INT_MAX) ? -1 : s31;
        }

        if (carry_seg >= 0 && lane == 0) {
            atomicAdd(&out[carry_seg], carry);
        }
    }
}

extern "C" void kernel_launch(void* const* d_in, const int* in_sizes, int n_in,
                              void* d_out, int out_size)
{
    const float* cv  = (const float*)d_in[0];
    const int*   idx = (const int*)d_in[1];
    const int*   seg = (const int*)d_in[2];
    float*       out = (float*)d_out;

    const int E = in_sizes[1];
    const int N = out_size;

    {
        int n4 = N / 4;
        int threads = 256;
        int blocks  = (n4 + threads - 1) / threads;
        if (blocks < 1) blocks = 1;
        zero_out_kernel<<<blocks, threads>>>((float4*)out, n4, out, N);
    }
    {
        long long n_warps  = ((long long)E + CHUNK - 1) / CHUNK;
        long long n_blocks = (n_warps + WARPS_PER_BLK - 1) / WARPS_PER_BLK;
        seg_sum_kernel<<<(int)n_blocks, 256>>>(cv, idx, seg, out, E);
    }
}

// round 6
// speedup vs baseline: 1.1123x; 1.0003x over previous
#include <cuda_runtime.h>
#include <cuda_bf16.h>
#include <limits.h>

// Sorted-segment-sum of gathered values:
//   out[s] = sum over j with seg[j]==s of cv[idx[j]]
// seg[] sorted ascending. Empty segments must be 0 (out is poisoned).
//
// Each warp handles ONE 256-edge chunk (8 edges/thread via 2x int4 loads).
// Per-thread run detection; interior runs flush directly; trailing runs
// combined by a ballot-based clamped warp scan. PDL overlaps the zero-init
// kernel with this kernel's (zero-independent) load prologue.

#define FULL 0xffffffffu
#define CHUNK 256          // edges per warp (8 per thread)
#define WARPS_PER_BLK 4    // block = 128 threads: finer CTA-slot recycling

__global__ void zero_out_kernel(float4* __restrict__ out4, int n4,
                                float* __restrict__ out, int n) {
    int i = blockIdx.x * blockDim.x + threadIdx.x;
    if (i < n4) out4[i] = make_float4(0.f, 0.f, 0.f, 0.f);
    int r = n4 * 4 + i;
    if (i < (n - n4 * 4)) out[r] = 0.0f;
#if __CUDA_ARCH__ >= 900
    cudaTriggerProgrammaticLaunchCompletion();
#endif
}

__global__ __launch_bounds__(128, 16)
void seg_sum_kernel(const float* __restrict__ cv,
                    const int*   __restrict__ idx,
                    const int*   __restrict__ seg,
                    float*       __restrict__ out,
                    int E)
{
    const int lane = threadIdx.x & 31;
    const long long w =
        (long long)blockIdx.x * WARPS_PER_BLK + (threadIdx.x >> 5);

    long long base = w * (long long)CHUNK;
    if (base >= (long long)E) {
#if __CUDA_ARCH__ >= 900
        cudaGridDependencySynchronize();
#endif
        return;
    }

    if (base + CHUNK <= (long long)E) {
        // ---------------- fast path: one full 256-edge chunk ----------------
        const int4* idx4 = (const int4*)idx;
        const int4* seg4 = (const int4*)seg;

        long long q = (base >> 2) + lane * 2;   // 2 consecutive int4 = 8 edges
        int4 sa = seg4[q];
        int4 sb = seg4[q + 1];
        int4 ia = idx4[q];
        int4 ib = idx4[q + 1];

        float v_arr[8];
        v_arr[0] = __ldg(&cv[ia.x]);
        v_arr[1] = __ldg(&cv[ia.y]);
        v_arr[2] = __ldg(&cv[ia.z]);
        v_arr[3] = __ldg(&cv[ia.w]);
        v_arr[4] = __ldg(&cv[ib.x]);
        v_arr[5] = __ldg(&cv[ib.y]);
        v_arr[6] = __ldg(&cv[ib.z]);
        v_arr[7] = __ldg(&cv[ib.w]);

        int s_arr[8] = { sa.x, sa.y, sa.z, sa.w, sb.x, sb.y, sb.z, sb.w };

#if __CUDA_ARCH__ >= 900
        // output writes below depend on the zero-init kernel
        cudaGridDependencySynchronize();
#endif

        // per-thread run detection over 8 consecutive edges
        float run = v_arr[0];
        int   rs  = s_arr[0];
        const int sfirst = s_arr[0];
        float lead = 0.0f;
        bool  leadDone = false;
        #pragma unroll
        for (int i = 1; i < 8; i++) {
            if (s_arr[i] == rs) {
                run += v_arr[i];
            } else {
                if (!leadDone) { lead = run; leadDone = true; }
                else           { atomicAdd(&out[rs], run); }  // interior: complete
                run = v_arr[i];
                rs  = s_arr[i];
            }
        }
        const float trail   = run;     // if allsame: total of all 8
        const int   slast   = rs;
        const bool  allsame = !leadDone;

        // connectivity with the preceding lane
        int  prev_slast = __shfl_up_sync(FULL, slast, 1);
        bool connected  = (lane != 0) && (prev_slast == sfirst);

        float sv = trail;
        bool  f  = (lane == 0) || !allsame || !connected;  // chain break

        // ballot-based clamped inclusive scan over trailing-run chain
        unsigned head_mask = __ballot_sync(FULL, f);       // bit0 always set
        unsigned mask_le   = head_mask & (FULL >> (31 - lane));
        int seg_start = 31 - __clz(mask_le);
        #pragma unroll
        for (int d = 1; d < 32; d <<= 1) {
            float y = __shfl_up_sync(FULL, sv, d);
            if (lane - d >= seg_start) sv += y;
        }

        // chain-sum ending at lane-1 (completed prefix for segment sfirst)
        float inc_prev = __shfl_up_sync(FULL, sv, 1);

        // flush this thread's leading run (complete since !allsame)
        if (!allsame) {
            float add = lead + (connected ? inc_prev : 0.0f);
            atomicAdd(&out[sfirst], add);
        }

        // trailing-run flush: complete if the next lane doesn't continue it
        int  next_sfirst    = __shfl_down_sync(FULL, sfirst, 1);
        bool next_connected = (lane < 31) && (next_sfirst == slast);
        if (!next_connected) {
            atomicAdd(&out[slast], sv);   // lane 31 always flushes its chain
        }
    } else {
        // ---------------- scalar tail path (last partial chunk) ----------------
#if __CUDA_ARCH__ >= 900
        cudaGridDependencySynchronize();
#endif
        long long lim = (long long)E;
        float carry     = 0.0f;
        int   carry_seg = -1;

        for (long long p = base; p < lim; p += 32) {
            long long j = p + lane;
            bool valid  = (j < lim);

            int   s = INT_MAX;
            float v = 0.0f;
            if (valid) {
                s = seg[j];
                v = __ldg(&cv[idx[j]]);
            }

            int  s_prev = __shfl_up_sync(FULL, s, 1);
            bool head   = (lane == 0) || (s != s_prev);
            unsigned head_mask = __ballot_sync(FULL, head);

            unsigned mask_le = head_mask & (FULL >> (31 - lane));
            int seg_start = 31 - __clz(mask_le);

            float x = v;
            #pragma unroll
            for (int d = 1; d < 32; d <<= 1) {
                float y = __shfl_up_sync(FULL, x, d);
                if (lane - d >= seg_start) x += y;
            }

            int s0 = __shfl_sync(FULL, s, 0);
            if (carry_seg == s0) {
                if (seg_start == 0) x += carry;
            } else if (carry_seg >= 0) {
                if (lane == 0) atomicAdd(&out[carry_seg], carry);
            }

            bool tail = (lane == 31) || ((head_mask >> (lane + 1)) & 1u);
            if (tail && lane != 31 && valid) {
                atomicAdd(&out[s], x);
            }

            carry   = __shfl_sync(FULL, x, 31);
            int s31 = __shfl_sync(FULL, s, 31);
            carry_seg = (s31 == INT_MAX) ? -1 : s31;
        }

        if (carry_seg >= 0 && lane == 0) {
            atomicAdd(&out[carry_seg], carry);
        }
    }
}

extern "C" void kernel_launch(void* const* d_in, const int* in_sizes, int n_in,
                              void* d_out, int out_size)
{
    const float* cv  = (const float*)d_in[0];
    const int*   idx = (const int*)d_in[1];
    const int*   seg = (const int*)d_in[2];
    float*       out = (float*)d_out;

    const int E = in_sizes[1];
    const int N = out_size;

    // 1) zero-init output (poisoned; empty segments must be 0)
    {
        int n4 = N / 4;
        int threads = 256;
        int blocks  = (n4 + threads - 1) / threads;
        if (blocks < 1) blocks = 1;
        zero_out_kernel<<<blocks, threads>>>((float4*)out, n4, out, N);
    }

    // 2) segmented sum, PDL-overlapped with the zero kernel's tail
    {
        long long n_warps  = ((long long)E + CHUNK - 1) / CHUNK;
        long long n_blocks = (n_warps + WARPS_PER_BLK - 1) / WARPS_PER_BLK;

        cudaLaunchConfig_t cfg = {};
        cfg.gridDim  = dim3((unsigned)n_blocks, 1, 1);
        cfg.blockDim = dim3(128, 1, 1);
        cfg.dynamicSmemBytes = 0;
        cfg.stream = 0;
        cudaLaunchAttribute attrs[1];
        attrs[0].id = cudaLaunchAttributeProgrammaticStreamSerialization;
        attrs[0].val.programmaticStreamSerializationAllowed = 1;
        cfg.attrs = attrs;
        cfg.numAttrs = 1;

        cudaError_t rc = cudaLaunchKernelEx(&cfg, seg_sum_kernel,
                                            cv, idx, seg, out, E);
        if (rc != cudaSuccess) {
            // fallback: plain serialized launch (device-side sync is a no-op)
            seg_sum_kernel<<<(int)n_blocks, 128>>>(cv, idx, seg, out, E);
        }
    }
}

// round 7
// speedup vs baseline: 1.1242x; 1.0107x over previous
#include <cuda_runtime.h>
#include <cuda_bf16.h>
#include <limits.h>

// Sorted-segment-sum of gathered values:
//   out[s] = sum over j with seg[j]==s of cv[idx[j]]
// seg[] sorted ascending. Empty segments must be 0 (out is poisoned).
//
// Each warp handles ONE 256-edge chunk (8 edges/thread via 2x int4 loads).
// Streaming idx/seg loads use __ldcs (evict-first) so the L1 stays reserved
// for the randomly-gathered child table. Per-thread run detection; interior
// runs flush directly; trailing runs combined by a ballot-based clamped warp
// scan. PDL overlaps the zero-init kernel with the load prologue.

#define FULL 0xffffffffu
#define CHUNK 256          // edges per warp (8 per thread)
#define WARPS_PER_BLK 8

__global__ void zero_out_kernel(float4* __restrict__ out4, int n4,
                                float* __restrict__ out, int n) {
    int i = blockIdx.x * blockDim.x + threadIdx.x;
    if (i < n4) out4[i] = make_float4(0.f, 0.f, 0.f, 0.f);
    int r = n4 * 4 + i;
    if (i < (n - n4 * 4)) out[r] = 0.0f;
#if __CUDA_ARCH__ >= 900
    cudaTriggerProgrammaticLaunchCompletion();
#endif
}

__global__ __launch_bounds__(256, 8)
void seg_sum_kernel(const float* __restrict__ cv,
                    const int*   __restrict__ idx,
                    const int*   __restrict__ seg,
                    float*       __restrict__ out,
                    int E)
{
    const int lane = threadIdx.x & 31;
    const long long w =
        (long long)blockIdx.x * WARPS_PER_BLK + (threadIdx.x >> 5);

    long long base = w * (long long)CHUNK;
    if (base >= (long long)E) {
#if __CUDA_ARCH__ >= 900
        cudaGridDependencySynchronize();
#endif
        return;
    }

    if (base + CHUNK <= (long long)E) {
        // ---------------- fast path: one full 256-edge chunk ----------------
        const int4* idx4 = (const int4*)idx;
        const int4* seg4 = (const int4*)seg;

        long long q = (base >> 2) + lane * 2;   // 2 consecutive int4 = 8 edges
        int4 sa = __ldcs(&seg4[q]);
        int4 sb = __ldcs(&seg4[q + 1]);
        int4 ia = __ldcs(&idx4[q]);
        int4 ib = __ldcs(&idx4[q + 1]);

        float v_arr[8];
        v_arr[0] = __ldg(&cv[ia.x]);
        v_arr[1] = __ldg(&cv[ia.y]);
        v_arr[2] = __ldg(&cv[ia.z]);
        v_arr[3] = __ldg(&cv[ia.w]);
        v_arr[4] = __ldg(&cv[ib.x]);
        v_arr[5] = __ldg(&cv[ib.y]);
        v_arr[6] = __ldg(&cv[ib.z]);
        v_arr[7] = __ldg(&cv[ib.w]);

        int s_arr[8] = { sa.x, sa.y, sa.z, sa.w, sb.x, sb.y, sb.z, sb.w };

#if __CUDA_ARCH__ >= 900
        // output writes below depend on the zero-init kernel
        cudaGridDependencySynchronize();
#endif

        // per-thread run detection over 8 consecutive edges
        float run = v_arr[0];
        int   rs  = s_arr[0];
        const int sfirst = s_arr[0];
        float lead = 0.0f;
        bool  leadDone = false;
        #pragma unroll
        for (int i = 1; i < 8; i++) {
            if (s_arr[i] == rs) {
                run += v_arr[i];
            } else {
                if (!leadDone) { lead = run; leadDone = true; }
                else           { atomicAdd(&out[rs], run); }  // interior: complete
                run = v_arr[i];
                rs  = s_arr[i];
            }
        }
        const float trail   = run;     // if allsame: total of all 8
        const int   slast   = rs;
        const bool  allsame = !leadDone;

        // connectivity with the preceding lane
        int  prev_slast = __shfl_up_sync(FULL, slast, 1);
        bool connected  = (lane != 0) && (prev_slast == sfirst);

        float sv = trail;
        bool  f  = (lane == 0) || !allsame || !connected;  // chain break

        // ballot-based clamped inclusive scan over trailing-run chain
        unsigned head_mask = __ballot_sync(FULL, f);       // bit0 always set
        unsigned mask_le   = head_mask & (FULL >> (31 - lane));
        int seg_start = 31 - __clz(mask_le);
        #pragma unroll
        for (int d = 1; d < 32; d <<= 1) {
            float y = __shfl_up_sync(FULL, sv, d);
            if (lane - d >= seg_start) sv += y;
        }

        // chain-sum ending at lane-1 (completed prefix for segment sfirst)
        float inc_prev = __shfl_up_sync(FULL, sv, 1);

        // flush this thread's leading run (complete since !allsame)
        if (!allsame) {
            float add = lead + (connected ? inc_prev : 0.0f);
            atomicAdd(&out[sfirst], add);
        }

        // trailing-run flush: complete if the next lane doesn't continue it
        int  next_sfirst    = __shfl_down_sync(FULL, sfirst, 1);
        bool next_connected = (lane < 31) && (next_sfirst == slast);
        if (!next_connected) {
            atomicAdd(&out[slast], sv);   // lane 31 always flushes its chain
        }
    } else {
        // ---------------- scalar tail path (last partial chunk) ----------------
#if __CUDA_ARCH__ >= 900
        cudaGridDependencySynchronize();
#endif
        long long lim = (long long)E;
        float carry     = 0.0f;
        int   carry_seg = -1;

        for (long long p = base; p < lim; p += 32) {
            long long j = p + lane;
            bool valid  = (j < lim);

            int   s = INT_MAX;
            float v = 0.0f;
            if (valid) {
                s = seg[j];
                v = __ldg(&cv[idx[j]]);
            }

            int  s_prev = __shfl_up_sync(FULL, s, 1);
            bool head   = (lane == 0) || (s != s_prev);
            unsigned head_mask = __ballot_sync(FULL, head);

            unsigned mask_le = head_mask & (FULL >> (31 - lane));
            int seg_start = 31 - __clz(mask_le);

            float x = v;
            #pragma unroll
            for (int d = 1; d < 32; d <<= 1) {
                float y = __shfl_up_sync(FULL, x, d);
                if (lane - d >= seg_start) x += y;
            }

            int s0 = __shfl_sync(FULL, s, 0);
            if (carry_seg == s0) {
                if (seg_start == 0) x += carry;
            } else if (carry_seg >= 0) {
                if (lane == 0) atomicAdd(&out[carry_seg], carry);
            }

            bool tail = (lane == 31) || ((head_mask >> (lane + 1)) & 1u);
            if (tail && lane != 31 && valid) {
                atomicAdd(&out[s], x);
            }

            carry   = __shfl_sync(FULL, x, 31);
            int s31 = __shfl_sync(FULL, s, 31);
            carry_seg = (s31 == INT_MAX) ? -1 : s31;
        }

        if (carry_seg >= 0 && lane == 0) {
            atomicAdd(&out[carry_seg], carry);
        }
    }
}

extern "C" void kernel_launch(void* const* d_in, const int* in_sizes, int n_in,
                              void* d_out, int out_size)
{
    const float* cv  = (const float*)d_in[0];
    const int*   idx = (const int*)d_in[1];
    const int*   seg = (const int*)d_in[2];
    float*       out = (float*)d_out;

    const int E = in_sizes[1];
    const int N = out_size;

    // 1) zero-init output (poisoned; empty segments must be 0)
    {
        int n4 = N / 4;
        int threads = 256;
        int blocks  = (n4 + threads - 1) / threads;
        if (blocks < 1) blocks = 1;
        zero_out_kernel<<<blocks, threads>>>((float4*)out, n4, out, N);
    }

    // 2) segmented sum, PDL-overlapped with the zero kernel's tail
    {
        long long n_warps  = ((long long)E + CHUNK - 1) / CHUNK;
        long long n_blocks = (n_warps + WARPS_PER_BLK - 1) / WARPS_PER_BLK;

        cudaLaunchConfig_t cfg = {};
        cfg.gridDim  = dim3((unsigned)n_blocks, 1, 1);
        cfg.blockDim = dim3(256, 1, 1);
        cfg.dynamicSmemBytes = 0;
        cfg.stream = 0;
        cudaLaunchAttribute attrs[1];
        attrs[0].id = cudaLaunchAttributeProgrammaticStreamSerialization;
        attrs[0].val.programmaticStreamSerializationAllowed = 1;
        cfg.attrs = attrs;
        cfg.numAttrs = 1;

        cudaError_t rc = cudaLaunchKernelEx(&cfg, seg_sum_kernel,
                                            cv, idx, seg, out, E);
        if (rc != cudaSuccess) {
            // fallback: plain serialized launch (device-side sync is a no-op)
            seg_sum_kernel<<<(int)n_blocks, 256>>>(cv, idx, seg, out, E);
        }
    }
}